// round 1
// baseline (speedup 1.0000x reference)
#include <cuda_runtime.h>
#include <cstddef>

// Problem constants
#define Bq 16
#define Tq 2048
#define Eq 1024
#define Sq 2000
#define HIDq 150
#define BT (Bq*Tq)          // 32768
#define N600 600
#define NSPAN (Bq*Sq)       // 32000
#define NCH 16              // cumsum chunks over T
#define CHT (Tq/NCH)        // 128

// ---------------- scratch (device globals; no allocation allowed) --------
__device__ float g_W600[Eq*N600];              // packed [Wa1 | Ws1_a | Ws1_b | Ws1_c]
__device__ float g_Y[(size_t)BT*N600];         // X @ W600
__device__ float g_attn[BT];                   // attention scalar per token
__device__ float g_csum[(size_t)Bq*(Tq+1)*Eq]; // prefix sums of weighted embeds
__device__ float g_ctot[Bq*NCH*Eq];            // chunk totals for csum
__device__ float g_scp[(size_t)Bq*(Tq+1)*HIDq];// prefix sums of attn * proj_c
__device__ float g_sctot[Bq*NCH*HIDq];
__device__ float g_h[(size_t)NSPAN*HIDq];      // relu(layer1) of score MLP

// ---------------- pack W600 ----------------------------------------------
__global__ void pack_w600(const float* __restrict__ Wa1, const float* __restrict__ Ws1) {
    int idx = blockIdx.x * blockDim.x + threadIdx.x;
    if (idx >= Eq * N600) return;
    int k = idx / N600, j = idx % N600;
    float v;
    if      (j < 150) v = Wa1[k*150 + j];
    else if (j < 300) v = Ws1[k*150 + (j-150)];
    else if (j < 450) v = Ws1[(1024+k)*150 + (j-300)];
    else              v = Ws1[(2048+k)*150 + (j-450)];
    g_W600[idx] = v;
}

// ---------------- SGEMM: Y[BT,600] = X[BT,1024] @ W600[1024,600] ---------
// BM=128 BN=64 BK=16, 256 threads, 8x4 per-thread tile.
__global__ __launch_bounds__(256) void sgemm600(const float* __restrict__ A) {
    __shared__ float As[16][128];
    __shared__ float Bs[16][64];
    int bm = blockIdx.x, bn = blockIdx.y;
    int tid = threadIdx.x;
    int tx = tid & 15, ty = tid >> 4;

    const float* Ab = A + (size_t)bm * 128 * Eq;
    float acc[8][4];
#pragma unroll
    for (int i = 0; i < 8; i++)
#pragma unroll
        for (int j = 0; j < 4; j++) acc[i][j] = 0.f;

    int aRow = tid >> 1;            // 0..127
    int aCol = (tid & 1) * 8;       // 0 or 8
    int bRow = tid >> 4;            // 0..15
    int bCol = (tid & 15) * 4;      // 0..60
    int colBase = bn * 64;

    for (int k0 = 0; k0 < Eq; k0 += 16) {
        float4 a0 = *(const float4*)(Ab + (size_t)aRow*Eq + k0 + aCol);
        float4 a1 = *(const float4*)(Ab + (size_t)aRow*Eq + k0 + aCol + 4);
        As[aCol+0][aRow] = a0.x; As[aCol+1][aRow] = a0.y;
        As[aCol+2][aRow] = a0.z; As[aCol+3][aRow] = a0.w;
        As[aCol+4][aRow] = a1.x; As[aCol+5][aRow] = a1.y;
        As[aCol+6][aRow] = a1.z; As[aCol+7][aRow] = a1.w;

        int gcol = colBase + bCol;
        float4 bv = make_float4(0.f, 0.f, 0.f, 0.f);
        if (gcol < N600)   // 600 % 4 == 0 -> float4 fully in/out; 16B aligned
            bv = *(const float4*)(g_W600 + (size_t)(k0 + bRow) * N600 + gcol);
        *(float4*)&Bs[bRow][bCol] = bv;
        __syncthreads();

#pragma unroll
        for (int k = 0; k < 16; k++) {
            float4 a0r = *(const float4*)&As[k][ty*8];
            float4 a1r = *(const float4*)&As[k][ty*8 + 4];
            float4 br  = *(const float4*)&Bs[k][tx*4];
            float ar[8] = {a0r.x,a0r.y,a0r.z,a0r.w,a1r.x,a1r.y,a1r.z,a1r.w};
            float bb[4] = {br.x,br.y,br.z,br.w};
#pragma unroll
            for (int i = 0; i < 8; i++)
#pragma unroll
                for (int j = 0; j < 4; j++) acc[i][j] += ar[i]*bb[j];
        }
        __syncthreads();
    }

    int row0 = bm*128 + ty*8;
    int col0 = colBase + tx*4;
#pragma unroll
    for (int i = 0; i < 8; i++)
#pragma unroll
        for (int j = 0; j < 4; j++)
            if (col0 + j < N600)
                g_Y[(size_t)(row0+i)*N600 + col0 + j] = acc[i][j];
}

// ---------------- MLP layers 2+3 (150->150 relu ->1) ----------------------
// X[row, k] (ld=ldx), optional bias+relu on layer-1 input; 32 rows per block.
__global__ __launch_bounds__(160) void mlp23_kernel(
    const float* __restrict__ X, int ldx,
    const float* __restrict__ b1,             // null -> X already biased+relu'd
    const float* __restrict__ W2, const float* __restrict__ b2,
    const float* __restrict__ W3, const float* __restrict__ b3,
    float* __restrict__ outp, int M)
{
    __shared__ float a1s[32][152];
    __shared__ float a2s[32][152];
    int base = blockIdx.x * 32;
    int tid = threadIdx.x;

    for (int idx = tid; idx < 32*150; idx += blockDim.x) {
        int t = idx / 150, k = idx % 150;
        int row = base + t;
        float v = 0.f;
        if (row < M) {
            v = X[(size_t)row*ldx + k];
            if (b1) v = fmaxf(v + b1[k], 0.f);
        }
        a1s[t][k] = v;
    }
    __syncthreads();

    int j = tid;
    if (j < 150) {
        float acc[32];
#pragma unroll
        for (int t = 0; t < 32; t++) acc[t] = b2[j];
        for (int k = 0; k < 150; k++) {
            float w = W2[k*150 + j];
#pragma unroll
            for (int t = 0; t < 32; t++) acc[t] += a1s[t][k] * w;
        }
#pragma unroll
        for (int t = 0; t < 32; t++) a2s[t][j] = fmaxf(acc[t], 0.f);
    }
    __syncthreads();

    if (tid < 32) {
        int row = base + tid;
        if (row < M) {
            float s = b3[0];
            for (int k = 0; k < 150; k++) s += a2s[tid][k] * W3[k];
            outp[row] = s;
        }
    }
}

// ---------------- cumsum of weighted embeds (2-pass) ----------------------
__global__ __launch_bounds__(128) void csum_p1(const float* __restrict__ emb) {
    int e = blockIdx.x * 128 + threadIdx.x;
    int c = blockIdx.y, b = blockIdx.z;
    const float* eb = emb + ((size_t)(b*Tq + c*CHT)) * Eq + e;
    const float* ab = g_attn + b*Tq + c*CHT;
    float s = 0.f;
    for (int t0 = 0; t0 < CHT; t0 += 8) {
        float v[8];
#pragma unroll
        for (int i = 0; i < 8; i++) v[i] = eb[(size_t)(t0+i)*Eq] * ab[t0+i];
#pragma unroll
        for (int i = 0; i < 8; i++) s += v[i];
    }
    g_ctot[(b*NCH + c)*Eq + e] = s;
}

__global__ __launch_bounds__(128) void csum_p2(const float* __restrict__ emb) {
    int e = blockIdx.x * 128 + threadIdx.x;
    int c = blockIdx.y, b = blockIdx.z;
    float off = 0.f;
    for (int cc = 0; cc < c; cc++) off += g_ctot[(b*NCH + cc)*Eq + e];
    const float* eb = emb + ((size_t)(b*Tq + c*CHT)) * Eq + e;
    const float* ab = g_attn + b*Tq + c*CHT;
    float* cb = g_csum + ((size_t)(b*(Tq+1) + c*CHT + 1)) * Eq + e;
    if (c == 0) g_csum[((size_t)b*(Tq+1))*Eq + e] = 0.f;
    float s = off;
    for (int t0 = 0; t0 < CHT; t0 += 8) {
        float v[8];
#pragma unroll
        for (int i = 0; i < 8; i++) v[i] = eb[(size_t)(t0+i)*Eq] * ab[t0+i];
#pragma unroll
        for (int i = 0; i < 8; i++) { s += v[i]; cb[(size_t)(t0+i)*Eq] = s; }
    }
}

// ---------------- cumsum of attn * proj_c (Y cols 450..599), 2-pass --------
__global__ __launch_bounds__(160) void scp_p1() {
    int j = threadIdx.x; if (j >= 150) return;
    int c = blockIdx.y, b = blockIdx.z;
    int row0 = b*Tq + c*CHT;
    float s = 0.f;
    for (int t = 0; t < CHT; t++)
        s += g_Y[(size_t)(row0+t)*N600 + 450 + j] * g_attn[row0+t];
    g_sctot[(b*NCH + c)*HIDq + j] = s;
}

__global__ __launch_bounds__(160) void scp_p2() {
    int j = threadIdx.x; if (j >= 150) return;
    int c = blockIdx.y, b = blockIdx.z;
    float off = 0.f;
    for (int cc = 0; cc < c; cc++) off += g_sctot[(b*NCH + cc)*HIDq + j];
    int row0 = b*Tq + c*CHT;
    float* sp = g_scp + ((size_t)(b*(Tq+1) + c*CHT + 1)) * HIDq + j;
    if (c == 0) g_scp[((size_t)b*(Tq+1))*HIDq + j] = 0.f;
    float s = off;
    for (int t = 0; t < CHT; t++) {
        s += g_Y[(size_t)(row0+t)*N600 + 450 + j] * g_attn[row0+t];
        sp[(size_t)t*HIDq] = s;
    }
}

// ---------------- span gather: write span_emb + score layer-1 --------------
__global__ __launch_bounds__(256) void span_kernel(
    const float* __restrict__ emb, const int* __restrict__ starts,
    const int* __restrict__ lengths, const int* __restrict__ nspans,
    const float* __restrict__ bs1, float* __restrict__ out)
{
    int s = blockIdx.x, b = blockIdx.y;
    int tid = threadIdx.x;
    int span = b*Sq + s;
    float4* o4 = (float4*)(out + (size_t)span * 3072);

    if (s >= nspans[b]) {
        float4 z = make_float4(0.f, 0.f, 0.f, 0.f);
        o4[tid] = z; o4[256 + tid] = z; o4[512 + tid] = z;
        if (tid < 150) g_h[(size_t)span*HIDq + tid] = fmaxf(bs1[tid], 0.f);
        return;
    }
    int st = starts[b*Sq + s];
    int en = st + lengths[b*Sq + s];

    const float4* e1 = (const float4*)(emb + ((size_t)(b*Tq + st)) * Eq);
    const float4* e2 = (const float4*)(emb + ((size_t)(b*Tq + en)) * Eq);
    const float4* c1 = (const float4*)(g_csum + ((size_t)(b*(Tq+1) + st)) * Eq);
    const float4* c2 = (const float4*)(g_csum + ((size_t)(b*(Tq+1) + en + 1)) * Eq);

    o4[tid]       = e1[tid];
    o4[256 + tid] = e2[tid];
    float4 A = c2[tid], Bv = c1[tid];
    o4[512 + tid] = make_float4(A.x-Bv.x, A.y-Bv.y, A.z-Bv.z, A.w-Bv.w);

    if (tid < 150) {
        int r1 = b*Tq + st, r2 = b*Tq + en;
        float v = g_Y[(size_t)r1*N600 + 150 + tid]
                + g_Y[(size_t)r2*N600 + 300 + tid]
                + g_scp[((size_t)(b*(Tq+1) + en + 1))*HIDq + tid]
                - g_scp[((size_t)(b*(Tq+1) + st))*HIDq + tid]
                + bs1[tid];
        g_h[(size_t)span*HIDq + tid] = fmaxf(v, 0.f);
    }
}

// ---------------- launcher -------------------------------------------------
extern "C" void kernel_launch(void* const* d_in, const int* in_sizes, int n_in,
                              void* d_out, int out_size) {
    const float* emb     = (const float*)d_in[0];
    const int*   starts  = (const int*)d_in[1];
    const int*   lengths = (const int*)d_in[2];
    const int*   nspans  = (const int*)d_in[3];
    const float* Wa1 = (const float*)d_in[4];
    const float* ba1 = (const float*)d_in[5];
    const float* Wa2 = (const float*)d_in[6];
    const float* ba2 = (const float*)d_in[7];
    const float* Wa3 = (const float*)d_in[8];
    const float* ba3 = (const float*)d_in[9];
    const float* Ws1 = (const float*)d_in[10];
    const float* bs1 = (const float*)d_in[11];
    const float* Ws2 = (const float*)d_in[12];
    const float* bs2 = (const float*)d_in[13];
    const float* Ws3 = (const float*)d_in[14];
    const float* bs3 = (const float*)d_in[15];
    float* out = (float*)d_out;

    float* pY = nullptr; float* pAttn = nullptr; float* pH = nullptr;
    cudaGetSymbolAddress((void**)&pY, g_Y);
    cudaGetSymbolAddress((void**)&pAttn, g_attn);
    cudaGetSymbolAddress((void**)&pH, g_h);

    // 1) pack fused weight matrix [Wa1 | Ws1_a | Ws1_b | Ws1_c]
    pack_w600<<<(Eq*N600 + 255)/256, 256>>>(Wa1, Ws1);

    // 2) big fused GEMM: Y = X @ W600  (attn layer1 pre-act + 3 score projections)
    sgemm600<<<dim3(BT/128, (N600 + 63)/64), 256>>>(emb);

    // 3) attention MLP layers 2+3 -> g_attn
    mlp23_kernel<<<(BT + 31)/32, 160>>>(pY, N600, ba1, Wa2, ba2, Wa3, ba3, pAttn, BT);

    // 4) prefix sums of attn-weighted embeds (full E) and of attn*proj_c
    csum_p1<<<dim3(Eq/128, NCH, Bq), 128>>>(emb);
    csum_p2<<<dim3(Eq/128, NCH, Bq), 128>>>(emb);
    scp_p1<<<dim3(1, NCH, Bq), 160>>>();
    scp_p2<<<dim3(1, NCH, Bq), 160>>>();

    // 5) span gather: span_emb output + score layer-1 (via linearity)
    span_kernel<<<dim3(Sq, Bq), 256>>>(emb, starts, lengths, nspans, bs1, out);

    // 6) score MLP layers 2+3 -> scores at tail of output
    mlp23_kernel<<<(NSPAN + 31)/32, 160>>>(pH, HIDq, nullptr, Ws2, bs2, Ws3, bs3,
                                           out + (size_t)NSPAN*3072, NSPAN);
}

// round 8
// speedup vs baseline: 1.7215x; 1.7215x over previous
#include <cuda_runtime.h>
#include <cuda_bf16.h>
#include <cstdint>
#include <cstddef>

// Problem constants
#define Bq 16
#define Tq 2048
#define Eq 1024
#define Sq 2000
#define HIDq 150
#define BT (Bq*Tq)          // 32768
#define NSPAN (Bq*Sq)       // 32000
#define NCH 16              // cumsum chunks over T
#define CHT (Tq/NCH)        // 128
#define LDY 640             // padded output cols of fused GEMM (600 used)

// GEMM tiling (mma.sync m16n8k16 bf16)
#define GBM 128
#define GBN 64
#define GBK 64
#define KCH (Eq/GBK)        // 16 chunks
#define ST_STAGE 49152      // A hi 16K + A lo 16K + B hi 8K + B lo 8K
#define G_SMEM (3*ST_STAGE) // 147456, 3-stage pipeline

// ---------------- scratch (device globals; no allocation allowed) --------
__device__ __nv_bfloat16 g_Ahi[(size_t)BT*Eq];
__device__ __nv_bfloat16 g_Alo[(size_t)BT*Eq];
__device__ __nv_bfloat16 g_Bhi[(size_t)LDY*Eq];   // [n][k] N-major rows (rows >=600 zero)
__device__ __nv_bfloat16 g_Blo[(size_t)LDY*Eq];
__device__ float g_Y[(size_t)BT*LDY];          // X @ W600 (padded to 640)
__device__ float g_attn[BT];                   // attention scalar per token
__device__ float g_csum[(size_t)Bq*(Tq+1)*Eq]; // prefix sums of weighted embeds
__device__ float g_ctot[Bq*NCH*Eq];            // chunk totals for csum
__device__ float g_scp[(size_t)Bq*(Tq+1)*HIDq];// prefix sums of attn * proj_c
__device__ float g_sctot[Bq*NCH*HIDq];
__device__ float g_h[(size_t)NSPAN*HIDq];      // relu(layer1) of score MLP

// ---------------- PTX helpers (sm_103 baseline ISA only) -------------------
__device__ __forceinline__ uint32_t smem_u32(const void* p) {
    uint32_t a;
    asm("{ .reg .u64 t; cvta.to.shared.u64 t, %1; cvt.u32.u64 %0, t; }" : "=r"(a) : "l"(p));
    return a;
}

#define CP_ASYNC16(dst, src) \
    asm volatile("cp.async.cg.shared.global [%0], [%1], 16;" :: "r"(dst), "l"(src) : "memory")
#define CP_COMMIT() asm volatile("cp.async.commit_group;" ::: "memory")

__device__ __forceinline__ uint32_t sw128(uint32_t off) { return off ^ ((off >> 3) & 0x70); }

__device__ __forceinline__ void ldmx4(uint32_t* r, uint32_t addr) {
    asm volatile("ldmatrix.sync.aligned.m8n8.x4.shared.b16 {%0,%1,%2,%3}, [%4];"
        : "=r"(r[0]), "=r"(r[1]), "=r"(r[2]), "=r"(r[3]) : "r"(addr));
}

__device__ __forceinline__ void mma16816(float* d, const uint32_t* a, const uint32_t* b) {
    asm volatile("mma.sync.aligned.m16n8k16.row.col.f32.bf16.bf16.f32 "
        "{%0,%1,%2,%3}, {%4,%5,%6,%7}, {%8,%9}, {%0,%1,%2,%3};"
        : "+f"(d[0]), "+f"(d[1]), "+f"(d[2]), "+f"(d[3])
        : "r"(a[0]), "r"(a[1]), "r"(a[2]), "r"(a[3]), "r"(b[0]), "r"(b[1]));
}

// ---------------- split conversions ---------------------------------------
__global__ __launch_bounds__(256) void convA(const float* __restrict__ x) {
    size_t i = ((size_t)blockIdx.x * 256 + threadIdx.x) * 8;
    float4 a = *(const float4*)(x + i);
    float4 b = *(const float4*)(x + i + 4);
    float v[8] = {a.x, a.y, a.z, a.w, b.x, b.y, b.z, b.w};
    __nv_bfloat16 h[8], l[8];
#pragma unroll
    for (int j = 0; j < 8; j++) {
        h[j] = __float2bfloat16_rn(v[j]);
        l[j] = __float2bfloat16_rn(v[j] - __bfloat162float(h[j]));
    }
    *(uint4*)&g_Ahi[i] = *(uint4*)h;
    *(uint4*)&g_Alo[i] = *(uint4*)l;
}

__global__ void convB(const float* __restrict__ Wa1, const float* __restrict__ Ws1) {
    int idx = blockIdx.x * blockDim.x + threadIdx.x;
    if (idx >= LDY * Eq) return;
    int n = idx / Eq, k = idx % Eq;
    float v = 0.f;
    if      (n < 150) v = Wa1[k*150 + n];
    else if (n < 300) v = Ws1[k*150 + (n-150)];
    else if (n < 450) v = Ws1[(1024+k)*150 + (n-300)];
    else if (n < 600) v = Ws1[(2048+k)*150 + (n-450)];
    __nv_bfloat16 h = __float2bfloat16_rn(v);
    g_Bhi[idx] = h;
    g_Blo[idx] = __float2bfloat16_rn(v - __bfloat162float(h));
}

// ---------------- HMMA bf16x3 GEMM: Y[BT,640] = X @ W ----------------------
__device__ __forceinline__ void load_g(uint32_t sbase, int bm, int n0, int k0, int tid) {
    // A hi/lo tiles: 128 rows x 64 bf16 (128B rows), 8 x 16B units/row
#pragma unroll
    for (int v = tid; v < 2048; v += 256) {
        int arr = v >> 10, u = v & 1023;
        int row = u >> 3, c = u & 7;
        const __nv_bfloat16* g = (arr ? g_Alo : g_Ahi) + (((size_t)(bm*GBM + row)) << 10) + k0 + c*8;
        CP_ASYNC16(sbase + (uint32_t)arr*16384u + sw128(row*128 + c*16), g);
    }
    // B hi/lo tiles: 64 rows x 64 bf16
#pragma unroll
    for (int v = tid; v < 1024; v += 256) {
        int arr = v >> 9, u = v & 511;
        int row = u >> 3, c = u & 7;
        const __nv_bfloat16* g = (arr ? g_Blo : g_Bhi) + (((size_t)(n0 + row)) << 10) + k0 + c*8;
        CP_ASYNC16(sbase + 32768u + (uint32_t)arr*8192u + sw128(row*128 + c*16), g);
    }
}

__global__ __launch_bounds__(256, 1) void gemm_hmma(float* __restrict__ Y) {
    extern __shared__ char smem[];
    uint32_t sb = smem_u32(smem);
    int tid = threadIdx.x, wid = tid >> 5, lane = tid & 31;
    int bn = blockIdx.x, bm = blockIdx.y;      // N fastest -> A tile shared in-wave
    int n0 = bn * GBN;
    int wm = (wid >> 1) * 32, wn = (wid & 1) * 32;  // 4x2 warp grid, 32x32 warp tile

    float acc[2][4][4];
#pragma unroll
    for (int i = 0; i < 2; i++)
#pragma unroll
        for (int j = 0; j < 4; j++)
#pragma unroll
            for (int q = 0; q < 4; q++) acc[i][j][q] = 0.f;

    load_g(sb, bm, n0, 0, tid);               CP_COMMIT();
    load_g(sb + ST_STAGE, bm, n0, GBK, tid);  CP_COMMIT();

    for (int i = 0; i < KCH; i++) {
        if (i < KCH-1) asm volatile("cp.async.wait_group 1;" ::: "memory");
        else           asm volatile("cp.async.wait_group 0;" ::: "memory");
        __syncthreads();
        if (i + 2 < KCH) {
            load_g(sb + (uint32_t)((i+2)%3)*ST_STAGE, bm, n0, (i+2)*GBK, tid);
            CP_COMMIT();
        }
        uint32_t aB = sb + (uint32_t)(i%3)*ST_STAGE;   // A hi; A lo at +16384
        uint32_t bB = aB + 32768u;                     // B hi; B lo at +8192
#pragma unroll
        for (int ks = 0; ks < 4; ks++) {
            int k0 = ks*16;
            // A fragments (two m16 tiles, hi+lo)
            int arow = wm + (lane & 15);
            int acol = k0 + ((lane >> 4) << 3);
            uint32_t aoff0 = sw128((uint32_t)(arow*128 + acol*2));
            uint32_t aoff1 = sw128((uint32_t)((arow+16)*128 + acol*2));
            uint32_t ah0[4], ah1[4], al0[4], al1[4];
            ldmx4(ah0, aB + aoff0);           ldmx4(ah1, aB + aoff1);
            ldmx4(al0, aB + 16384u + aoff0);  ldmx4(al1, aB + 16384u + aoff1);
            // B fragments (four n8 tiles = 2x ldmx4, hi+lo)
            int brow = wn + ((lane >> 4) << 3) + (lane & 7);
            int bcol = k0 + (((lane >> 3) & 1) << 3);
            uint32_t boff0 = sw128((uint32_t)(brow*128 + bcol*2));
            uint32_t boff1 = sw128((uint32_t)((brow+16)*128 + bcol*2));
            uint32_t bhf[8], blf[8];
            ldmx4(bhf, bB + boff0);           ldmx4(bhf+4, bB + boff1);
            ldmx4(blf, bB + 8192u + boff0);   ldmx4(blf+4, bB + 8192u + boff1);
#pragma unroll
            for (int nt = 0; nt < 4; nt++) {
                mma16816(acc[0][nt], ah0, &bhf[nt*2]);   // hi*hi
                mma16816(acc[1][nt], ah1, &bhf[nt*2]);
                mma16816(acc[0][nt], ah0, &blf[nt*2]);   // hi*lo
                mma16816(acc[1][nt], ah1, &blf[nt*2]);
                mma16816(acc[0][nt], al0, &bhf[nt*2]);   // lo*hi
                mma16816(acc[1][nt], al1, &bhf[nt*2]);
            }
        }
    }

    // epilogue: direct stores (8B pairs, row-major Y)
    int rbase = bm*GBM + wm;
    int cbase = n0 + wn;
#pragma unroll
    for (int mt = 0; mt < 2; mt++)
#pragma unroll
        for (int nt = 0; nt < 4; nt++) {
            int r = rbase + mt*16 + (lane >> 2);
            int cc = cbase + nt*8 + ((lane & 3) << 1);
            *(float2*)&Y[(size_t)r*LDY + cc]     = make_float2(acc[mt][nt][0], acc[mt][nt][1]);
            *(float2*)&Y[(size_t)(r+8)*LDY + cc] = make_float2(acc[mt][nt][2], acc[mt][nt][3]);
        }
}

// ---------------- MLP layers 2+3 (150->150 relu ->1) ----------------------
__global__ __launch_bounds__(160) void mlp23_kernel(
    const float* __restrict__ X, int ldx,
    const float* __restrict__ b1,
    const float* __restrict__ W2, const float* __restrict__ b2,
    const float* __restrict__ W3, const float* __restrict__ b3,
    float* __restrict__ outp, int M)
{
    __shared__ float a1s[32][152];
    __shared__ float a2s[32][152];
    int base = blockIdx.x * 32;
    int tid = threadIdx.x;

    for (int idx = tid; idx < 32*150; idx += blockDim.x) {
        int t = idx / 150, k = idx % 150;
        int row = base + t;
        float v = 0.f;
        if (row < M) {
            v = X[(size_t)row*ldx + k];
            if (b1) v = fmaxf(v + b1[k], 0.f);
        }
        a1s[t][k] = v;
    }
    __syncthreads();

    int j = tid;
    if (j < 150) {
        float acc[32];
#pragma unroll
        for (int t = 0; t < 32; t++) acc[t] = b2[j];
        for (int k = 0; k < 150; k++) {
            float w = W2[k*150 + j];
#pragma unroll
            for (int t = 0; t < 32; t++) acc[t] += a1s[t][k] * w;
        }
#pragma unroll
        for (int t = 0; t < 32; t++) a2s[t][j] = fmaxf(acc[t], 0.f);
    }
    __syncthreads();

    if (tid < 32) {
        int row = base + tid;
        if (row < M) {
            float s = b3[0];
            for (int k = 0; k < 150; k++) s += a2s[tid][k] * W3[k];
            outp[row] = s;
        }
    }
}

// ---------------- cumsum of weighted embeds (2-pass) ----------------------
__global__ __launch_bounds__(128) void csum_p1(const float* __restrict__ emb) {
    int e = blockIdx.x * 128 + threadIdx.x;
    int c = blockIdx.y, b = blockIdx.z;
    const float* eb = emb + ((size_t)(b*Tq + c*CHT)) * Eq + e;
    const float* ab = g_attn + b*Tq + c*CHT;
    float s = 0.f;
    for (int t0 = 0; t0 < CHT; t0 += 8) {
        float v[8];
#pragma unroll
        for (int i = 0; i < 8; i++) v[i] = eb[(size_t)(t0+i)*Eq] * ab[t0+i];
#pragma unroll
        for (int i = 0; i < 8; i++) s += v[i];
    }
    g_ctot[(b*NCH + c)*Eq + e] = s;
}

__global__ __launch_bounds__(128) void csum_p2(const float* __restrict__ emb) {
    int e = blockIdx.x * 128 + threadIdx.x;
    int c = blockIdx.y, b = blockIdx.z;
    float off = 0.f;
    for (int cc = 0; cc < c; cc++) off += g_ctot[(b*NCH + cc)*Eq + e];
    const float* eb = emb + ((size_t)(b*Tq + c*CHT)) * Eq + e;
    const float* ab = g_attn + b*Tq + c*CHT;
    float* cb = g_csum + ((size_t)(b*(Tq+1) + c*CHT + 1)) * Eq + e;
    if (c == 0) g_csum[((size_t)b*(Tq+1))*Eq + e] = 0.f;
    float s = off;
    for (int t0 = 0; t0 < CHT; t0 += 8) {
        float v[8];
#pragma unroll
        for (int i = 0; i < 8; i++) v[i] = eb[(size_t)(t0+i)*Eq] * ab[t0+i];
#pragma unroll
        for (int i = 0; i < 8; i++) { s += v[i]; cb[(size_t)(t0+i)*Eq] = s; }
    }
}

// ---------------- cumsum of attn * proj_c (Y cols 450..599), 2-pass --------
__global__ __launch_bounds__(160) void scp_p1() {
    int j = threadIdx.x; if (j >= 150) return;
    int c = blockIdx.y, b = blockIdx.z;
    int row0 = b*Tq + c*CHT;
    float s = 0.f;
    for (int t = 0; t < CHT; t++)
        s += g_Y[(size_t)(row0+t)*LDY + 450 + j] * g_attn[row0+t];
    g_sctot[(b*NCH + c)*HIDq + j] = s;
}

__global__ __launch_bounds__(160) void scp_p2() {
    int j = threadIdx.x; if (j >= 150) return;
    int c = blockIdx.y, b = blockIdx.z;
    float off = 0.f;
    for (int cc = 0; cc < c; cc++) off += g_sctot[(b*NCH + cc)*HIDq + j];
    int row0 = b*Tq + c*CHT;
    float* sp = g_scp + ((size_t)(b*(Tq+1) + c*CHT + 1)) * HIDq + j;
    if (c == 0) g_scp[((size_t)b*(Tq+1))*HIDq + j] = 0.f;
    float s = off;
    for (int t = 0; t < CHT; t++) {
        s += g_Y[(size_t)(row0+t)*LDY + 450 + j] * g_attn[row0+t];
        sp[(size_t)t*HIDq] = s;
    }
}

// ---------------- span gather: write span_emb + score layer-1 --------------
__global__ __launch_bounds__(256) void span_kernel(
    const float* __restrict__ emb, const int* __restrict__ starts,
    const int* __restrict__ lengths, const int* __restrict__ nspans,
    const float* __restrict__ bs1, float* __restrict__ out)
{
    int s = blockIdx.x, b = blockIdx.y;
    int tid = threadIdx.x;
    int span = b*Sq + s;
    float4* o4 = (float4*)(out + (size_t)span * 3072);

    if (s >= nspans[b]) {
        float4 z = make_float4(0.f, 0.f, 0.f, 0.f);
        o4[tid] = z; o4[256 + tid] = z; o4[512 + tid] = z;
        if (tid < 150) g_h[(size_t)span*HIDq + tid] = fmaxf(bs1[tid], 0.f);
        return;
    }
    int st = starts[b*Sq + s];
    int en = st + lengths[b*Sq + s];

    const float4* e1 = (const float4*)(emb + ((size_t)(b*Tq + st)) * Eq);
    const float4* e2 = (const float4*)(emb + ((size_t)(b*Tq + en)) * Eq);
    const float4* c1 = (const float4*)(g_csum + ((size_t)(b*(Tq+1) + st)) * Eq);
    const float4* c2 = (const float4*)(g_csum + ((size_t)(b*(Tq+1) + en + 1)) * Eq);

    o4[tid]       = e1[tid];
    o4[256 + tid] = e2[tid];
    float4 A = c2[tid], Bv = c1[tid];
    o4[512 + tid] = make_float4(A.x-Bv.x, A.y-Bv.y, A.z-Bv.z, A.w-Bv.w);

    if (tid < 150) {
        int r1 = b*Tq + st, r2 = b*Tq + en;
        float v = g_Y[(size_t)r1*LDY + 150 + tid]
                + g_Y[(size_t)r2*LDY + 300 + tid]
                + g_scp[((size_t)(b*(Tq+1) + en + 1))*HIDq + tid]
                - g_scp[((size_t)(b*(Tq+1) + st))*HIDq + tid]
                + bs1[tid];
        g_h[(size_t)span*HIDq + tid] = fmaxf(v, 0.f);
    }
}

// ---------------- launcher -------------------------------------------------
extern "C" void kernel_launch(void* const* d_in, const int* in_sizes, int n_in,
                              void* d_out, int out_size) {
    const float* emb     = (const float*)d_in[0];
    const int*   starts  = (const int*)d_in[1];
    const int*   lengths = (const int*)d_in[2];
    const int*   nspans  = (const int*)d_in[3];
    const float* Wa1 = (const float*)d_in[4];
    const float* ba1 = (const float*)d_in[5];
    const float* Wa2 = (const float*)d_in[6];
    const float* ba2 = (const float*)d_in[7];
    const float* Wa3 = (const float*)d_in[8];
    const float* ba3 = (const float*)d_in[9];
    const float* Ws1 = (const float*)d_in[10];
    const float* bs1 = (const float*)d_in[11];
    const float* Ws2 = (const float*)d_in[12];
    const float* bs2 = (const float*)d_in[13];
    const float* Ws3 = (const float*)d_in[14];
    const float* bs3 = (const float*)d_in[15];
    float* out = (float*)d_out;

    float* pY = nullptr; float* pAttn = nullptr; float* pH = nullptr;
    cudaGetSymbolAddress((void**)&pY, g_Y);
    cudaGetSymbolAddress((void**)&pAttn, g_attn);
    cudaGetSymbolAddress((void**)&pH, g_h);

    cudaFuncSetAttribute(gemm_hmma, cudaFuncAttributeMaxDynamicSharedMemorySize, G_SMEM);

    // 1) bf16 hi/lo splits of X and packed/transposed W
    convA<<<BT*Eq/8/256, 256>>>(emb);
    convB<<<(LDY*Eq + 255)/256, 256>>>(Wa1, Ws1);

    // 2) tensor-core GEMM via mma.sync: Y = X @ [Wa1 | Ws1_a | Ws1_b | Ws1_c]
    gemm_hmma<<<dim3(LDY/GBN, BT/GBM), 256, G_SMEM>>>(pY);

    // 3) attention MLP layers 2+3 -> g_attn
    mlp23_kernel<<<(BT + 31)/32, 160>>>(pY, LDY, ba1, Wa2, ba2, Wa3, ba3, pAttn, BT);

    // 4) prefix sums of attn-weighted embeds (full E) and of attn*proj_c
    csum_p1<<<dim3(Eq/128, NCH, Bq), 128>>>(emb);
    csum_p2<<<dim3(Eq/128, NCH, Bq), 128>>>(emb);
    scp_p1<<<dim3(1, NCH, Bq), 160>>>();
    scp_p2<<<dim3(1, NCH, Bq), 160>>>();

    // 5) span gather: span_emb output + score layer-1 (via linearity)
    span_kernel<<<dim3(Sq, Bq), 256>>>(emb, starts, lengths, nspans, bs1, out);

    // 6) score MLP layers 2+3 -> scores at tail of output
    mlp23_kernel<<<(NSPAN + 31)/32, 160>>>(pH, HIDq, nullptr, Ws2, bs2, Ws3, bs3,
                                           out + (size_t)NSPAN*3072, NSPAN);
}

// round 14
// speedup vs baseline: 1.7299x; 1.0049x over previous
#include <cuda_runtime.h>
#include <cuda_bf16.h>
#include <cstdint>
#include <cstddef>

// Problem constants
#define Bq 16
#define Tq 2048
#define Eq 1024
#define Sq 2000
#define HIDq 150
#define BT (Bq*Tq)          // 32768
#define NSPAN (Bq*Sq)       // 32000
#define NCH 16              // cumsum chunks over T
#define CHT (Tq/NCH)        // 128
#define LDY 640             // padded output cols of fused GEMM (600 used)

// GEMM tiling (mma.sync m16n8k16 bf16)
#define GBM 128
#define GBN 64
#define GBK 64
#define KCH (Eq/GBK)        // 16 chunks
#define ST_STAGE 49152      // A hi 16K + A lo 16K + B hi 8K + B lo 8K
#define G_SMEM (3*ST_STAGE) // 147456, 3-stage pipeline

// MLP tiling: 64 rows/block, lane columns padded to 160 (5 groups x 32)
#define MROWS 64
#define LDW 160
#define MLP_A1   0
#define MLP_W2   (MROWS*152*4)                 // 38912 (a1s: 64 x 152)
#define MLP_B2   (MLP_W2 + 150*LDW*4)          // 38912 + 96000 = 134912
#define MLP_W3   (MLP_B2 + LDW*4)              // 135552
#define MLP_SMEM (MLP_W3 + LDW*4)              // 136192

// ---------------- scratch (device globals; no allocation allowed) --------
__device__ __nv_bfloat16 g_Ahi[(size_t)BT*Eq];
__device__ __nv_bfloat16 g_Alo[(size_t)BT*Eq];
__device__ __nv_bfloat16 g_Bhi[(size_t)LDY*Eq];   // [n][k] N-major rows (rows >=600 zero)
__device__ __nv_bfloat16 g_Blo[(size_t)LDY*Eq];
__device__ float g_Y[(size_t)BT*LDY];          // X @ W600 (padded to 640)
__device__ float g_attn[BT];                   // attention scalar per token
__device__ float g_csum[(size_t)Bq*(Tq+1)*Eq]; // prefix sums of weighted embeds
__device__ float g_ctot[Bq*NCH*Eq];            // chunk totals for csum
__device__ float g_scp[(size_t)Bq*(Tq+1)*HIDq];// prefix sums of attn * proj_c
__device__ float g_sctot[Bq*NCH*HIDq];
__device__ float g_h[(size_t)NSPAN*HIDq];      // relu(layer1) of score MLP

// ---------------- PTX helpers (sm_103 baseline ISA only) -------------------
__device__ __forceinline__ uint32_t smem_u32(const void* p) {
    uint32_t a;
    asm("{ .reg .u64 t; cvta.to.shared.u64 t, %1; cvt.u32.u64 %0, t; }" : "=r"(a) : "l"(p));
    return a;
}

#define CP_ASYNC16(dst, src) \
    asm volatile("cp.async.cg.shared.global [%0], [%1], 16;" :: "r"(dst), "l"(src) : "memory")
#define CP_COMMIT() asm volatile("cp.async.commit_group;" ::: "memory")

__device__ __forceinline__ uint32_t sw128(uint32_t off) { return off ^ ((off >> 3) & 0x70); }

__device__ __forceinline__ void ldmx4(uint32_t* r, uint32_t addr) {
    asm volatile("ldmatrix.sync.aligned.m8n8.x4.shared.b16 {%0,%1,%2,%3}, [%4];"
        : "=r"(r[0]), "=r"(r[1]), "=r"(r[2]), "=r"(r[3]) : "r"(addr));
}

__device__ __forceinline__ void mma16816(float* d, const uint32_t* a, const uint32_t* b) {
    asm volatile("mma.sync.aligned.m16n8k16.row.col.f32.bf16.bf16.f32 "
        "{%0,%1,%2,%3}, {%4,%5,%6,%7}, {%8,%9}, {%0,%1,%2,%3};"
        : "+f"(d[0]), "+f"(d[1]), "+f"(d[2]), "+f"(d[3])
        : "r"(a[0]), "r"(a[1]), "r"(a[2]), "r"(a[3]), "r"(b[0]), "r"(b[1]));
}

// ---------------- split conversions ---------------------------------------
__global__ __launch_bounds__(256) void convA(const float* __restrict__ x) {
    size_t i = ((size_t)blockIdx.x * 256 + threadIdx.x) * 8;
    float4 a = *(const float4*)(x + i);
    float4 b = *(const float4*)(x + i + 4);
    float v[8] = {a.x, a.y, a.z, a.w, b.x, b.y, b.z, b.w};
    __nv_bfloat16 h[8], l[8];
#pragma unroll
    for (int j = 0; j < 8; j++) {
        h[j] = __float2bfloat16_rn(v[j]);
        l[j] = __float2bfloat16_rn(v[j] - __bfloat162float(h[j]));
    }
    *(uint4*)&g_Ahi[i] = *(uint4*)h;
    *(uint4*)&g_Alo[i] = *(uint4*)l;
}

__global__ void convB(const float* __restrict__ Wa1, const float* __restrict__ Ws1) {
    int idx = blockIdx.x * blockDim.x + threadIdx.x;
    if (idx >= LDY * Eq) return;
    int n = idx / Eq, k = idx % Eq;
    float v = 0.f;
    if      (n < 150) v = Wa1[k*150 + n];
    else if (n < 300) v = Ws1[k*150 + (n-150)];
    else if (n < 450) v = Ws1[(1024+k)*150 + (n-300)];
    else if (n < 600) v = Ws1[(2048+k)*150 + (n-450)];
    __nv_bfloat16 h = __float2bfloat16_rn(v);
    g_Bhi[idx] = h;
    g_Blo[idx] = __float2bfloat16_rn(v - __bfloat162float(h));
}

// ---------------- HMMA bf16x3 GEMM: Y[BT,640] = X @ W ----------------------
__device__ __forceinline__ void load_g(uint32_t sbase, int bm, int n0, int k0, int tid) {
#pragma unroll
    for (int v = tid; v < 2048; v += 256) {
        int arr = v >> 10, u = v & 1023;
        int row = u >> 3, c = u & 7;
        const __nv_bfloat16* g = (arr ? g_Alo : g_Ahi) + (((size_t)(bm*GBM + row)) << 10) + k0 + c*8;
        CP_ASYNC16(sbase + (uint32_t)arr*16384u + sw128(row*128 + c*16), g);
    }
#pragma unroll
    for (int v = tid; v < 1024; v += 256) {
        int arr = v >> 9, u = v & 511;
        int row = u >> 3, c = u & 7;
        const __nv_bfloat16* g = (arr ? g_Blo : g_Bhi) + (((size_t)(n0 + row)) << 10) + k0 + c*8;
        CP_ASYNC16(sbase + 32768u + (uint32_t)arr*8192u + sw128(row*128 + c*16), g);
    }
}

__global__ __launch_bounds__(256, 1) void gemm_hmma(float* __restrict__ Y) {
    extern __shared__ char smem[];
    uint32_t sb = smem_u32(smem);
    int tid = threadIdx.x, wid = tid >> 5, lane = tid & 31;
    int bn = blockIdx.x, bm = blockIdx.y;
    int n0 = bn * GBN;
    int wm = (wid >> 1) * 32, wn = (wid & 1) * 32;

    float acc[2][4][4];
#pragma unroll
    for (int i = 0; i < 2; i++)
#pragma unroll
        for (int j = 0; j < 4; j++)
#pragma unroll
            for (int q = 0; q < 4; q++) acc[i][j][q] = 0.f;

    load_g(sb, bm, n0, 0, tid);               CP_COMMIT();
    load_g(sb + ST_STAGE, bm, n0, GBK, tid);  CP_COMMIT();

    for (int i = 0; i < KCH; i++) {
        if (i < KCH-1) asm volatile("cp.async.wait_group 1;" ::: "memory");
        else           asm volatile("cp.async.wait_group 0;" ::: "memory");
        __syncthreads();
        if (i + 2 < KCH) {
            load_g(sb + (uint32_t)((i+2)%3)*ST_STAGE, bm, n0, (i+2)*GBK, tid);
            CP_COMMIT();
        }
        uint32_t aB = sb + (uint32_t)(i%3)*ST_STAGE;
        uint32_t bB = aB + 32768u;
#pragma unroll
        for (int ks = 0; ks < 4; ks++) {
            int k0 = ks*16;
            int arow = wm + (lane & 15);
            int acol = k0 + ((lane >> 4) << 3);
            uint32_t aoff0 = sw128((uint32_t)(arow*128 + acol*2));
            uint32_t aoff1 = sw128((uint32_t)((arow+16)*128 + acol*2));
            uint32_t ah0[4], ah1[4], al0[4], al1[4];
            ldmx4(ah0, aB + aoff0);           ldmx4(ah1, aB + aoff1);
            ldmx4(al0, aB + 16384u + aoff0);  ldmx4(al1, aB + 16384u + aoff1);
            int brow = wn + ((lane >> 4) << 3) + (lane & 7);
            int bcol = k0 + (((lane >> 3) & 1) << 3);
            uint32_t boff0 = sw128((uint32_t)(brow*128 + bcol*2));
            uint32_t boff1 = sw128((uint32_t)((brow+16)*128 + bcol*2));
            uint32_t bhf[8], blf[8];
            ldmx4(bhf, bB + boff0);           ldmx4(bhf+4, bB + boff1);
            ldmx4(blf, bB + 8192u + boff0);   ldmx4(blf+4, bB + 8192u + boff1);
#pragma unroll
            for (int nt = 0; nt < 4; nt++) {
                mma16816(acc[0][nt], ah0, &bhf[nt*2]);
                mma16816(acc[1][nt], ah1, &bhf[nt*2]);
                mma16816(acc[0][nt], ah0, &blf[nt*2]);
                mma16816(acc[1][nt], ah1, &blf[nt*2]);
                mma16816(acc[0][nt], al0, &bhf[nt*2]);
                mma16816(acc[1][nt], al1, &bhf[nt*2]);
            }
        }
    }

    int rbase = bm*GBM + wm;
    int cbase = n0 + wn;
#pragma unroll
    for (int mt = 0; mt < 2; mt++)
#pragma unroll
        for (int nt = 0; nt < 4; nt++) {
            int r = rbase + mt*16 + (lane >> 2);
            int cc = cbase + nt*8 + ((lane & 3) << 1);
            *(float2*)&Y[(size_t)r*LDY + cc]     = make_float2(acc[mt][nt][0], acc[mt][nt][1]);
            *(float2*)&Y[(size_t)(r+8)*LDY + cc] = make_float2(acc[mt][nt][2], acc[mt][nt][3]);
        }
}

// ---------------- MLP layers 2+3, register-tiled ---------------------------
// Block: 256 thr / 8 warps, 64 rows. Warp ty: rows ty*8..+8. Lane tx: cols tx+32c (c<5, pad 160).
__global__ __launch_bounds__(256) void mlp23_kernel(
    const float* __restrict__ X, int ldx,
    const float* __restrict__ b1,
    const float* __restrict__ W2, const float* __restrict__ b2,
    const float* __restrict__ W3, const float* __restrict__ b3,
    float* __restrict__ outp, int M)
{
    extern __shared__ char smem[];
    float* a1s = (float*)(smem + MLP_A1);   // [64][152]
    float* w2s = (float*)(smem + MLP_W2);   // [150][160] zero-padded
    float* b2s = (float*)(smem + MLP_B2);   // [160] zero-padded
    float* w3s = (float*)(smem + MLP_W3);   // [160] zero-padded
    int tid = threadIdx.x, tx = tid & 31, ty = tid >> 5;
    int base = blockIdx.x * MROWS;

    // stage a1 (bias+relu if b1), W2 (zero-padded to 160 cols), b2, W3
    for (int idx = tid; idx < MROWS*152; idx += 256) {
        int t = idx / 152, k = idx % 152;
        int row = base + t;
        float v = 0.f;
        if (row < M && k < 150) {
            v = X[(size_t)row*ldx + k];
            if (b1) v = fmaxf(v + b1[k], 0.f);
        }
        a1s[idx] = v;
    }
    for (int idx = tid; idx < 150*LDW; idx += 256) {
        int k = idx / LDW, j = idx % LDW;
        w2s[idx] = (j < 150) ? W2[k*150 + j] : 0.f;
    }
    if (tid < LDW) {
        b2s[tid] = (tid < 150) ? b2[tid] : 0.f;
        w3s[tid] = (tid < 150) ? W3[tid] : 0.f;
    }
    __syncthreads();

    float acc[8][5];
#pragma unroll
    for (int i = 0; i < 8; i++)
#pragma unroll
        for (int c = 0; c < 5; c++) acc[i][c] = 0.f;

    const float* arow = a1s + ty*8*152;
#pragma unroll 2
    for (int k = 0; k < 150; k++) {
        float av[8];
#pragma unroll
        for (int i = 0; i < 8; i++) av[i] = arow[i*152 + k];     // broadcast LDS
        float wv[5];
#pragma unroll
        for (int c = 0; c < 5; c++) wv[c] = w2s[k*LDW + tx + 32*c];
#pragma unroll
        for (int i = 0; i < 8; i++)
#pragma unroll
            for (int c = 0; c < 5; c++) acc[i][c] += av[i]*wv[c];
    }

    // layer 3: relu + dot(W3) in registers, warp reduce, lane 0 stores.
    // Padded lanes (j>=150): w2s/b2s/w3s are 0 -> contribution exactly 0.
    float bb3 = b3[0];
#pragma unroll
    for (int i = 0; i < 8; i++) {
        float part = 0.f;
#pragma unroll
        for (int c = 0; c < 5; c++) {
            int j = tx + 32*c;
            float a2 = fmaxf(acc[i][c] + b2s[j], 0.f);
            part += a2 * w3s[j];
        }
#pragma unroll
        for (int off = 16; off; off >>= 1)
            part += __shfl_xor_sync(0xffffffffu, part, off);
        int row = base + ty*8 + i;
        if (tx == 0 && row < M) outp[row] = part + bb3;
    }
}

// ---------------- cumsum of weighted embeds (2-pass) ----------------------
__global__ __launch_bounds__(128) void csum_p1(const float* __restrict__ emb) {
    int e = blockIdx.x * 128 + threadIdx.x;
    int c = blockIdx.y, b = blockIdx.z;
    const float* eb = emb + ((size_t)(b*Tq + c*CHT)) * Eq + e;
    const float* ab = g_attn + b*Tq + c*CHT;
    float s = 0.f;
    for (int t0 = 0; t0 < CHT; t0 += 8) {
        float v[8];
#pragma unroll
        for (int i = 0; i < 8; i++) v[i] = eb[(size_t)(t0+i)*Eq] * ab[t0+i];
#pragma unroll
        for (int i = 0; i < 8; i++) s += v[i];
    }
    g_ctot[(b*NCH + c)*Eq + e] = s;
}

__global__ __launch_bounds__(128) void csum_p2(const float* __restrict__ emb) {
    int e = blockIdx.x * 128 + threadIdx.x;
    int c = blockIdx.y, b = blockIdx.z;
    float off = 0.f;
    for (int cc = 0; cc < c; cc++) off += g_ctot[(b*NCH + cc)*Eq + e];
    const float* eb = emb + ((size_t)(b*Tq + c*CHT)) * Eq + e;
    const float* ab = g_attn + b*Tq + c*CHT;
    float* cb = g_csum + ((size_t)(b*(Tq+1) + c*CHT + 1)) * Eq + e;
    if (c == 0) g_csum[((size_t)b*(Tq+1))*Eq + e] = 0.f;
    float s = off;
    for (int t0 = 0; t0 < CHT; t0 += 8) {
        float v[8];
#pragma unroll
        for (int i = 0; i < 8; i++) v[i] = eb[(size_t)(t0+i)*Eq] * ab[t0+i];
#pragma unroll
        for (int i = 0; i < 8; i++) { s += v[i]; cb[(size_t)(t0+i)*Eq] = s; }
    }
}

// ---------------- cumsum of attn * proj_c (Y cols 450..599), 2-pass --------
__global__ __launch_bounds__(160) void scp_p1() {
    int j = threadIdx.x; if (j >= 150) return;
    int c = blockIdx.y, b = blockIdx.z;
    int row0 = b*Tq + c*CHT;
    float s = 0.f;
    for (int t = 0; t < CHT; t++)
        s += g_Y[(size_t)(row0+t)*LDY + 450 + j] * g_attn[row0+t];
    g_sctot[(b*NCH + c)*HIDq + j] = s;
}

__global__ __launch_bounds__(160) void scp_p2() {
    int j = threadIdx.x; if (j >= 150) return;
    int c = blockIdx.y, b = blockIdx.z;
    float off = 0.f;
    for (int cc = 0; cc < c; cc++) off += g_sctot[(b*NCH + cc)*HIDq + j];
    int row0 = b*Tq + c*CHT;
    float* sp = g_scp + ((size_t)(b*(Tq+1) + c*CHT + 1)) * HIDq + j;
    if (c == 0) g_scp[((size_t)b*(Tq+1))*HIDq + j] = 0.f;
    float s = off;
    for (int t = 0; t < CHT; t++) {
        s += g_Y[(size_t)(row0+t)*LDY + 450 + j] * g_attn[row0+t];
        sp[(size_t)t*HIDq] = s;
    }
}

// ---------------- span gather: write span_emb + score layer-1 --------------
__global__ __launch_bounds__(256) void span_kernel(
    const float* __restrict__ emb, const int* __restrict__ starts,
    const int* __restrict__ lengths, const int* __restrict__ nspans,
    const float* __restrict__ bs1, float* __restrict__ out)
{
    int s = blockIdx.x, b = blockIdx.y;
    int tid = threadIdx.x;
    int span = b*Sq + s;
    float4* o4 = (float4*)(out + (size_t)span * 3072);

    if (s >= nspans[b]) {
        float4 z = make_float4(0.f, 0.f, 0.f, 0.f);
        o4[tid] = z; o4[256 + tid] = z; o4[512 + tid] = z;
        if (tid < 150) g_h[(size_t)span*HIDq + tid] = fmaxf(bs1[tid], 0.f);
        return;
    }
    int st = starts[b*Sq + s];
    int en = st + lengths[b*Sq + s];

    const float4* e1 = (const float4*)(emb + ((size_t)(b*Tq + st)) * Eq);
    const float4* e2 = (const float4*)(emb + ((size_t)(b*Tq + en)) * Eq);
    const float4* c1 = (const float4*)(g_csum + ((size_t)(b*(Tq+1) + st)) * Eq);
    const float4* c2 = (const float4*)(g_csum + ((size_t)(b*(Tq+1) + en + 1)) * Eq);

    o4[tid]       = e1[tid];
    o4[256 + tid] = e2[tid];
    float4 A = c2[tid], Bv = c1[tid];
    o4[512 + tid] = make_float4(A.x-Bv.x, A.y-Bv.y, A.z-Bv.z, A.w-Bv.w);

    if (tid < 150) {
        int r1 = b*Tq + st, r2 = b*Tq + en;
        float v = g_Y[(size_t)r1*LDY + 150 + tid]
                + g_Y[(size_t)r2*LDY + 300 + tid]
                + g_scp[((size_t)(b*(Tq+1) + en + 1))*HIDq + tid]
                - g_scp[((size_t)(b*(Tq+1) + st))*HIDq + tid]
                + bs1[tid];
        g_h[(size_t)span*HIDq + tid] = fmaxf(v, 0.f);
    }
}

// ---------------- launcher -------------------------------------------------
extern "C" void kernel_launch(void* const* d_in, const int* in_sizes, int n_in,
                              void* d_out, int out_size) {
    const float* emb     = (const float*)d_in[0];
    const int*   starts  = (const int*)d_in[1];
    const int*   lengths = (const int*)d_in[2];
    const int*   nspans  = (const int*)d_in[3];
    const float* Wa1 = (const float*)d_in[4];
    const float* ba1 = (const float*)d_in[5];
    const float* Wa2 = (const float*)d_in[6];
    const float* ba2 = (const float*)d_in[7];
    const float* Wa3 = (const float*)d_in[8];
    const float* ba3 = (const float*)d_in[9];
    const float* Ws1 = (const float*)d_in[10];
    const float* bs1 = (const float*)d_in[11];
    const float* Ws2 = (const float*)d_in[12];
    const float* bs2 = (const float*)d_in[13];
    const float* Ws3 = (const float*)d_in[14];
    const float* bs3 = (const float*)d_in[15];
    float* out = (float*)d_out;

    float* pY = nullptr; float* pAttn = nullptr; float* pH = nullptr;
    cudaGetSymbolAddress((void**)&pY, g_Y);
    cudaGetSymbolAddress((void**)&pAttn, g_attn);
    cudaGetSymbolAddress((void**)&pH, g_h);

    cudaFuncSetAttribute(gemm_hmma, cudaFuncAttributeMaxDynamicSharedMemorySize, G_SMEM);
    cudaFuncSetAttribute(mlp23_kernel, cudaFuncAttributeMaxDynamicSharedMemorySize, MLP_SMEM);

    // 1) bf16 hi/lo splits of X and packed/transposed W
    convA<<<BT*Eq/8/256, 256>>>(emb);
    convB<<<(LDY*Eq + 255)/256, 256>>>(Wa1, Ws1);

    // 2) tensor-core GEMM via mma.sync: Y = X @ [Wa1 | Ws1_a | Ws1_b | Ws1_c]
    gemm_hmma<<<dim3(LDY/GBN, BT/GBM), 256, G_SMEM>>>(pY);

    // 3) attention MLP layers 2+3 -> g_attn
    mlp23_kernel<<<BT/MROWS, 256, MLP_SMEM>>>(pY, LDY, ba1, Wa2, ba2, Wa3, ba3, pAttn, BT);

    // 4) prefix sums of attn-weighted embeds (full E) and of attn*proj_c
    csum_p1<<<dim3(Eq/128, NCH, Bq), 128>>>(emb);
    csum_p2<<<dim3(Eq/128, NCH, Bq), 128>>>(emb);
    scp_p1<<<dim3(1, NCH, Bq), 160>>>();
    scp_p2<<<dim3(1, NCH, Bq), 160>>>();

    // 5) span gather: span_emb output + score layer-1 (via linearity)
    span_kernel<<<dim3(Sq, Bq), 256>>>(emb, starts, lengths, nspans, bs1, out);

    // 6) score MLP layers 2+3 -> scores at tail of output
    mlp23_kernel<<<NSPAN/MROWS, 256, MLP_SMEM>>>(pH, HIDq, nullptr, Ws2, bs2, Ws3, bs3,
                                                 out + (size_t)NSPAN*3072, NSPAN);
}

// round 17
// speedup vs baseline: 1.9219x; 1.1110x over previous
#include <cuda_runtime.h>
#include <cuda_bf16.h>
#include <cstdint>
#include <cstddef>

// Problem constants
#define Bq 16
#define Tq 2048
#define Eq 1024
#define Sq 2000
#define HIDq 150
#define BT (Bq*Tq)          // 32768
#define NSPAN (Bq*Sq)       // 32000
#define NCH 16              // cumsum chunks over T
#define CHT (Tq/NCH)        // 128
#define LDY 640             // padded output cols of fused GEMM (600 used)

// GEMM tiling (mma.sync m16n8k16 bf16)
#define GBM 128
#define GBN 64
#define GBK 64
#define KCH (Eq/GBK)        // 16 chunks
#define ST_STAGE 49152      // A hi 16K + A lo 16K + B hi 8K + B lo 8K
#define G_SMEM (3*ST_STAGE) // 147456, 3-stage pipeline

// MLP tiling: 64 rows/block, lane columns padded to 160; W2 staged in 2 halves of 75 k-rows
#define MROWS 64
#define LDW 160
#define KHALF 75
#define MLP_A1   0
#define MLP_W2   (MROWS*152*4)                 // 38912 (a1s: 64 x 152)
#define MLP_B2   (MLP_W2 + KHALF*LDW*4)        // 38912 + 48000 = 86912
#define MLP_W3   (MLP_B2 + LDW*4)              // 87552
#define MLP_SMEM (MLP_W3 + LDW*4)              // 88192  -> 2 CTAs/SM

// ---------------- scratch (device globals; no allocation allowed) --------
__device__ __nv_bfloat16 g_Ahi[(size_t)BT*Eq];
__device__ __nv_bfloat16 g_Alo[(size_t)BT*Eq];
__device__ __nv_bfloat16 g_Bhi[(size_t)LDY*Eq];   // [n][k] N-major rows (rows >=600 zero)
__device__ __nv_bfloat16 g_Blo[(size_t)LDY*Eq];
__device__ float g_Y[(size_t)BT*LDY];          // X @ W600 (padded to 640)
__device__ float g_attn[BT];                   // attention scalar per token
__device__ float g_csum[(size_t)Bq*(Tq+1)*Eq]; // prefix sums of weighted embeds
__device__ float g_ctot[Bq*NCH*Eq];            // chunk totals for csum
__device__ float g_scp[(size_t)Bq*(Tq+1)*HIDq];// prefix sums of attn * proj_c
__device__ float g_sctot[Bq*NCH*HIDq];
__device__ float g_h[(size_t)NSPAN*HIDq];      // relu(layer1) of score MLP

// ---------------- PTX helpers (sm_103 baseline ISA only) -------------------
__device__ __forceinline__ uint32_t smem_u32(const void* p) {
    uint32_t a;
    asm("{ .reg .u64 t; cvta.to.shared.u64 t, %1; cvt.u32.u64 %0, t; }" : "=r"(a) : "l"(p));
    return a;
}

#define CP_ASYNC16(dst, src) \
    asm volatile("cp.async.cg.shared.global [%0], [%1], 16;" :: "r"(dst), "l"(src) : "memory")
#define CP_COMMIT() asm volatile("cp.async.commit_group;" ::: "memory")

__device__ __forceinline__ uint32_t sw128(uint32_t off) { return off ^ ((off >> 3) & 0x70); }

__device__ __forceinline__ void ldmx4(uint32_t* r, uint32_t addr) {
    asm volatile("ldmatrix.sync.aligned.m8n8.x4.shared.b16 {%0,%1,%2,%3}, [%4];"
        : "=r"(r[0]), "=r"(r[1]), "=r"(r[2]), "=r"(r[3]) : "r"(addr));
}

__device__ __forceinline__ void mma16816(float* d, const uint32_t* a, const uint32_t* b) {
    asm volatile("mma.sync.aligned.m16n8k16.row.col.f32.bf16.bf16.f32 "
        "{%0,%1,%2,%3}, {%4,%5,%6,%7}, {%8,%9}, {%0,%1,%2,%3};"
        : "+f"(d[0]), "+f"(d[1]), "+f"(d[2]), "+f"(d[3])
        : "r"(a[0]), "r"(a[1]), "r"(a[2]), "r"(a[3]), "r"(b[0]), "r"(b[1]));
}

// ---------------- split conversions ---------------------------------------
__global__ __launch_bounds__(256) void convA(const float* __restrict__ x) {
    size_t i = ((size_t)blockIdx.x * 256 + threadIdx.x) * 8;
    float4 a = *(const float4*)(x + i);
    float4 b = *(const float4*)(x + i + 4);
    float v[8] = {a.x, a.y, a.z, a.w, b.x, b.y, b.z, b.w};
    __nv_bfloat16 h[8], l[8];
#pragma unroll
    for (int j = 0; j < 8; j++) {
        h[j] = __float2bfloat16_rn(v[j]);
        l[j] = __float2bfloat16_rn(v[j] - __bfloat162float(h[j]));
    }
    *(uint4*)&g_Ahi[i] = *(uint4*)h;
    *(uint4*)&g_Alo[i] = *(uint4*)l;
}

__global__ void convB(const float* __restrict__ Wa1, const float* __restrict__ Ws1) {
    int idx = blockIdx.x * blockDim.x + threadIdx.x;
    if (idx >= LDY * Eq) return;
    int n = idx / Eq, k = idx % Eq;
    float v = 0.f;
    if      (n < 150) v = Wa1[k*150 + n];
    else if (n < 300) v = Ws1[k*150 + (n-150)];
    else if (n < 450) v = Ws1[(1024+k)*150 + (n-300)];
    else if (n < 600) v = Ws1[(2048+k)*150 + (n-450)];
    __nv_bfloat16 h = __float2bfloat16_rn(v);
    g_Bhi[idx] = h;
    g_Blo[idx] = __float2bfloat16_rn(v - __bfloat162float(h));
}

// ---------------- HMMA bf16x3 GEMM: Y[BT,640] = X @ W ----------------------
__device__ __forceinline__ void load_g(uint32_t sbase, int bm, int n0, int k0, int tid) {
#pragma unroll
    for (int v = tid; v < 2048; v += 256) {
        int arr = v >> 10, u = v & 1023;
        int row = u >> 3, c = u & 7;
        const __nv_bfloat16* g = (arr ? g_Alo : g_Ahi) + (((size_t)(bm*GBM + row)) << 10) + k0 + c*8;
        CP_ASYNC16(sbase + (uint32_t)arr*16384u + sw128(row*128 + c*16), g);
    }
#pragma unroll
    for (int v = tid; v < 1024; v += 256) {
        int arr = v >> 9, u = v & 511;
        int row = u >> 3, c = u & 7;
        const __nv_bfloat16* g = (arr ? g_Blo : g_Bhi) + (((size_t)(n0 + row)) << 10) + k0 + c*8;
        CP_ASYNC16(sbase + 32768u + (uint32_t)arr*8192u + sw128(row*128 + c*16), g);
    }
}

__global__ __launch_bounds__(256, 1) void gemm_hmma(float* __restrict__ Y) {
    extern __shared__ char smem[];
    uint32_t sb = smem_u32(smem);
    int tid = threadIdx.x, wid = tid >> 5, lane = tid & 31;
    int bn = blockIdx.x, bm = blockIdx.y;
    int n0 = bn * GBN;
    int wm = (wid >> 1) * 32, wn = (wid & 1) * 32;

    float acc[2][4][4];
#pragma unroll
    for (int i = 0; i < 2; i++)
#pragma unroll
        for (int j = 0; j < 4; j++)
#pragma unroll
            for (int q = 0; q < 4; q++) acc[i][j][q] = 0.f;

    load_g(sb, bm, n0, 0, tid);               CP_COMMIT();
    load_g(sb + ST_STAGE, bm, n0, GBK, tid);  CP_COMMIT();

    for (int i = 0; i < KCH; i++) {
        if (i < KCH-1) asm volatile("cp.async.wait_group 1;" ::: "memory");
        else           asm volatile("cp.async.wait_group 0;" ::: "memory");
        __syncthreads();
        if (i + 2 < KCH) {
            load_g(sb + (uint32_t)((i+2)%3)*ST_STAGE, bm, n0, (i+2)*GBK, tid);
            CP_COMMIT();
        }
        uint32_t aB = sb + (uint32_t)(i%3)*ST_STAGE;
        uint32_t bB = aB + 32768u;
#pragma unroll
        for (int ks = 0; ks < 4; ks++) {
            int k0 = ks*16;
            int arow = wm + (lane & 15);
            int acol = k0 + ((lane >> 4) << 3);
            uint32_t aoff0 = sw128((uint32_t)(arow*128 + acol*2));
            uint32_t aoff1 = sw128((uint32_t)((arow+16)*128 + acol*2));
            uint32_t ah0[4], ah1[4], al0[4], al1[4];
            ldmx4(ah0, aB + aoff0);           ldmx4(ah1, aB + aoff1);
            ldmx4(al0, aB + 16384u + aoff0);  ldmx4(al1, aB + 16384u + aoff1);
            int brow = wn + ((lane >> 4) << 3) + (lane & 7);
            int bcol = k0 + (((lane >> 3) & 1) << 3);
            uint32_t boff0 = sw128((uint32_t)(brow*128 + bcol*2));
            uint32_t boff1 = sw128((uint32_t)((brow+16)*128 + bcol*2));
            uint32_t bhf[8], blf[8];
            ldmx4(bhf, bB + boff0);           ldmx4(bhf+4, bB + boff1);
            ldmx4(blf, bB + 8192u + boff0);   ldmx4(blf+4, bB + 8192u + boff1);
#pragma unroll
            for (int nt = 0; nt < 4; nt++) {
                mma16816(acc[0][nt], ah0, &bhf[nt*2]);
                mma16816(acc[1][nt], ah1, &bhf[nt*2]);
                mma16816(acc[0][nt], ah0, &blf[nt*2]);
                mma16816(acc[1][nt], ah1, &blf[nt*2]);
                mma16816(acc[0][nt], al0, &bhf[nt*2]);
                mma16816(acc[1][nt], al1, &bhf[nt*2]);
            }
        }
    }

    int rbase = bm*GBM + wm;
    int cbase = n0 + wn;
#pragma unroll
    for (int mt = 0; mt < 2; mt++)
#pragma unroll
        for (int nt = 0; nt < 4; nt++) {
            int r = rbase + mt*16 + (lane >> 2);
            int cc = cbase + nt*8 + ((lane & 3) << 1);
            *(float2*)&Y[(size_t)r*LDY + cc]     = make_float2(acc[mt][nt][0], acc[mt][nt][1]);
            *(float2*)&Y[(size_t)(r+8)*LDY + cc] = make_float2(acc[mt][nt][2], acc[mt][nt][3]);
        }
}

// ---------------- MLP layers 2+3, register-tiled, 2-CTA/SM -----------------
// Block: 256 thr / 8 warps, 64 rows. Warp ty: rows ty*8..+8. Lane tx: cols tx+32c (c<5, pad 160).
// W2 staged in 2 halves of KHALF k-rows so smem fits 2 CTAs/SM (4 warps/SMSP).
__global__ __launch_bounds__(256, 2) void mlp23_kernel(
    const float* __restrict__ X, int ldx,
    const float* __restrict__ b1,
    const float* __restrict__ W2, const float* __restrict__ b2,
    const float* __restrict__ W3, const float* __restrict__ b3,
    float* __restrict__ outp, int M)
{
    extern __shared__ char smem[];
    float* a1s = (float*)(smem + MLP_A1);   // [64][152]
    float* w2s = (float*)(smem + MLP_W2);   // [KHALF][160] zero-padded
    float* b2s = (float*)(smem + MLP_B2);   // [160] zero-padded
    float* w3s = (float*)(smem + MLP_W3);   // [160] zero-padded
    int tid = threadIdx.x, tx = tid & 31, ty = tid >> 5;
    int base = blockIdx.x * MROWS;

    // stage a1 (bias+relu if b1), b2, W3
    for (int idx = tid; idx < MROWS*152; idx += 256) {
        int t = idx / 152, k = idx % 152;
        int row = base + t;
        float v = 0.f;
        if (row < M && k < 150) {
            v = X[(size_t)row*ldx + k];
            if (b1) v = fmaxf(v + b1[k], 0.f);
        }
        a1s[idx] = v;
    }
    if (tid < LDW) {
        b2s[tid] = (tid < 150) ? b2[tid] : 0.f;
        w3s[tid] = (tid < 150) ? W3[tid] : 0.f;
    }

    float acc[8][5];
#pragma unroll
    for (int i = 0; i < 8; i++)
#pragma unroll
        for (int c = 0; c < 5; c++) acc[i][c] = 0.f;

    const float* arow = a1s + ty*8*152;

    for (int half = 0; half < 2; half++) {
        int kbase = half * KHALF;
        __syncthreads();   // protect w2s reuse (and a1 staging on first pass)
        for (int idx = tid; idx < KHALF*LDW; idx += 256) {
            int k = idx / LDW, j = idx % LDW;
            w2s[idx] = (j < 150) ? W2[(kbase + k)*150 + j] : 0.f;
        }
        __syncthreads();

#pragma unroll 3
        for (int k = 0; k < KHALF; k++) {
            float av[8];
#pragma unroll
            for (int i = 0; i < 8; i++) av[i] = arow[i*152 + kbase + k];  // broadcast LDS
            float wv[5];
#pragma unroll
            for (int c = 0; c < 5; c++) wv[c] = w2s[k*LDW + tx + 32*c];
#pragma unroll
            for (int i = 0; i < 8; i++)
#pragma unroll
                for (int c = 0; c < 5; c++) acc[i][c] += av[i]*wv[c];
        }
    }

    // layer 3: relu + dot(W3) in registers, warp reduce, lane 0 stores.
    // Padded lanes (j>=150): w2s/b2s/w3s are 0 -> contribution exactly 0.
    float bb3 = b3[0];
#pragma unroll
    for (int i = 0; i < 8; i++) {
        float part = 0.f;
#pragma unroll
        for (int c = 0; c < 5; c++) {
            int j = tx + 32*c;
            float a2 = fmaxf(acc[i][c] + b2s[j], 0.f);
            part += a2 * w3s[j];
        }
#pragma unroll
        for (int off = 16; off; off >>= 1)
            part += __shfl_xor_sync(0xffffffffu, part, off);
        int row = base + ty*8 + i;
        if (tx == 0 && row < M) outp[row] = part + bb3;
    }
}

// ---------------- cumsum of weighted embeds (2-pass) ----------------------
__global__ __launch_bounds__(128) void csum_p1(const float* __restrict__ emb) {
    int e = blockIdx.x * 128 + threadIdx.x;
    int c = blockIdx.y, b = blockIdx.z;
    const float* eb = emb + ((size_t)(b*Tq + c*CHT)) * Eq + e;
    const float* ab = g_attn + b*Tq + c*CHT;
    float s = 0.f;
    for (int t0 = 0; t0 < CHT; t0 += 8) {
        float v[8];
#pragma unroll
        for (int i = 0; i < 8; i++) v[i] = eb[(size_t)(t0+i)*Eq] * ab[t0+i];
#pragma unroll
        for (int i = 0; i < 8; i++) s += v[i];
    }
    g_ctot[(b*NCH + c)*Eq + e] = s;
}

__global__ __launch_bounds__(128) void csum_p2(const float* __restrict__ emb) {
    int e = blockIdx.x * 128 + threadIdx.x;
    int c = blockIdx.y, b = blockIdx.z;
    float off = 0.f;
    for (int cc = 0; cc < c; cc++) off += g_ctot[(b*NCH + cc)*Eq + e];
    const float* eb = emb + ((size_t)(b*Tq + c*CHT)) * Eq + e;
    const float* ab = g_attn + b*Tq + c*CHT;
    float* cb = g_csum + ((size_t)(b*(Tq+1) + c*CHT + 1)) * Eq + e;
    if (c == 0) g_csum[((size_t)b*(Tq+1))*Eq + e] = 0.f;
    float s = off;
    for (int t0 = 0; t0 < CHT; t0 += 8) {
        float v[8];
#pragma unroll
        for (int i = 0; i < 8; i++) v[i] = eb[(size_t)(t0+i)*Eq] * ab[t0+i];
#pragma unroll
        for (int i = 0; i < 8; i++) { s += v[i]; cb[(size_t)(t0+i)*Eq] = s; }
    }
}

// ---------------- cumsum of attn * proj_c (Y cols 450..599), 2-pass --------
__global__ __launch_bounds__(160) void scp_p1() {
    int j = threadIdx.x; if (j >= 150) return;
    int c = blockIdx.y, b = blockIdx.z;
    int row0 = b*Tq + c*CHT;
    float s = 0.f;
    for (int t = 0; t < CHT; t++)
        s += g_Y[(size_t)(row0+t)*LDY + 450 + j] * g_attn[row0+t];
    g_sctot[(b*NCH + c)*HIDq + j] = s;
}

__global__ __launch_bounds__(160) void scp_p2() {
    int j = threadIdx.x; if (j >= 150) return;
    int c = blockIdx.y, b = blockIdx.z;
    float off = 0.f;
    for (int cc = 0; cc < c; cc++) off += g_sctot[(b*NCH + cc)*HIDq + j];
    int row0 = b*Tq + c*CHT;
    float* sp = g_scp + ((size_t)(b*(Tq+1) + c*CHT + 1)) * HIDq + j;
    if (c == 0) g_scp[((size_t)b*(Tq+1))*HIDq + j] = 0.f;
    float s = off;
    for (int t = 0; t < CHT; t++) {
        s += g_Y[(size_t)(row0+t)*LDY + 450 + j] * g_attn[row0+t];
        sp[(size_t)t*HIDq] = s;
    }
}

// ---------------- span gather: write span_emb + score layer-1 --------------
__global__ __launch_bounds__(256) void span_kernel(
    const float* __restrict__ emb, const int* __restrict__ starts,
    const int* __restrict__ lengths, const int* __restrict__ nspans,
    const float* __restrict__ bs1, float* __restrict__ out)
{
    int s = blockIdx.x, b = blockIdx.y;
    int tid = threadIdx.x;
    int span = b*Sq + s;
    float4* o4 = (float4*)(out + (size_t)span * 3072);

    if (s >= nspans[b]) {
        float4 z = make_float4(0.f, 0.f, 0.f, 0.f);
        o4[tid] = z; o4[256 + tid] = z; o4[512 + tid] = z;
        if (tid < 150) g_h[(size_t)span*HIDq + tid] = fmaxf(bs1[tid], 0.f);
        return;
    }
    int st = starts[b*Sq + s];
    int en = st + lengths[b*Sq + s];

    const float4* e1 = (const float4*)(emb + ((size_t)(b*Tq + st)) * Eq);
    const float4* e2 = (const float4*)(emb + ((size_t)(b*Tq + en)) * Eq);
    const float4* c1 = (const float4*)(g_csum + ((size_t)(b*(Tq+1) + st)) * Eq);
    const float4* c2 = (const float4*)(g_csum + ((size_t)(b*(Tq+1) + en + 1)) * Eq);

    o4[tid]       = e1[tid];
    o4[256 + tid] = e2[tid];
    float4 A = c2[tid], Bv = c1[tid];
    o4[512 + tid] = make_float4(A.x-Bv.x, A.y-Bv.y, A.z-Bv.z, A.w-Bv.w);

    if (tid < 150) {
        int r1 = b*Tq + st, r2 = b*Tq + en;
        float v = g_Y[(size_t)r1*LDY + 150 + tid]
                + g_Y[(size_t)r2*LDY + 300 + tid]
                + g_scp[((size_t)(b*(Tq+1) + en + 1))*HIDq + tid]
                - g_scp[((size_t)(b*(Tq+1) + st))*HIDq + tid]
                + bs1[tid];
        g_h[(size_t)span*HIDq + tid] = fmaxf(v, 0.f);
    }
}

// ---------------- launcher -------------------------------------------------
extern "C" void kernel_launch(void* const* d_in, const int* in_sizes, int n_in,
                              void* d_out, int out_size) {
    const float* emb     = (const float*)d_in[0];
    const int*   starts  = (const int*)d_in[1];
    const int*   lengths = (const int*)d_in[2];
    const int*   nspans  = (const int*)d_in[3];
    const float* Wa1 = (const float*)d_in[4];
    const float* ba1 = (const float*)d_in[5];
    const float* Wa2 = (const float*)d_in[6];
    const float* ba2 = (const float*)d_in[7];
    const float* Wa3 = (const float*)d_in[8];
    const float* ba3 = (const float*)d_in[9];
    const float* Ws1 = (const float*)d_in[10];
    const float* bs1 = (const float*)d_in[11];
    const float* Ws2 = (const float*)d_in[12];
    const float* bs2 = (const float*)d_in[13];
    const float* Ws3 = (const float*)d_in[14];
    const float* bs3 = (const float*)d_in[15];
    float* out = (float*)d_out;

    float* pY = nullptr; float* pAttn = nullptr; float* pH = nullptr;
    cudaGetSymbolAddress((void**)&pY, g_Y);
    cudaGetSymbolAddress((void**)&pAttn, g_attn);
    cudaGetSymbolAddress((void**)&pH, g_h);

    cudaFuncSetAttribute(gemm_hmma, cudaFuncAttributeMaxDynamicSharedMemorySize, G_SMEM);
    cudaFuncSetAttribute(mlp23_kernel, cudaFuncAttributeMaxDynamicSharedMemorySize, MLP_SMEM);

    // 1) bf16 hi/lo splits of X and packed/transposed W
    convA<<<BT*Eq/8/256, 256>>>(emb);
    convB<<<(LDY*Eq + 255)/256, 256>>>(Wa1, Ws1);

    // 2) tensor-core GEMM via mma.sync: Y = X @ [Wa1 | Ws1_a | Ws1_b | Ws1_c]
    gemm_hmma<<<dim3(LDY/GBN, BT/GBM), 256, G_SMEM>>>(pY);

    // 3) attention MLP layers 2+3 -> g_attn
    mlp23_kernel<<<BT/MROWS, 256, MLP_SMEM>>>(pY, LDY, ba1, Wa2, ba2, Wa3, ba3, pAttn, BT);

    // 4) prefix sums of attn-weighted embeds (full E) and of attn*proj_c
    csum_p1<<<dim3(Eq/128, NCH, Bq), 128>>>(emb);
    csum_p2<<<dim3(Eq/128, NCH, Bq), 128>>>(emb);
    scp_p1<<<dim3(1, NCH, Bq), 160>>>();
    scp_p2<<<dim3(1, NCH, Bq), 160>>>();

    // 5) span gather: span_emb output + score layer-1 (via linearity)
    span_kernel<<<dim3(Sq, Bq), 256>>>(emb, starts, lengths, nspans, bs1, out);

    // 6) score MLP layers 2+3 -> scores at tail of output
    mlp23_kernel<<<NSPAN/MROWS, 256, MLP_SMEM>>>(pH, HIDq, nullptr, Ws2, bs2, Ws3, bs3,
                                                 out + (size_t)NSPAN*3072, NSPAN);
}